// round 11
// baseline (speedup 1.0000x reference)
#include <cuda_runtime.h>
#include <cuda_bf16.h>
#include <math.h>

#define LSEQ   1024
#define DMODEL 1024
#define NHEADS 16
#define DHEAD  64
#define NBATCH 8
#define NROWS  (NBATCH * LSEQ)   // 8192

static __device__ float g_Q[NROWS * DMODEL];
static __device__ float g_K[NROWS * DMODEL];
static __device__ float g_V[NROWS * DMODEL];
static __device__ float g_CTX[NROWS * DMODEL];
static __device__ float g_Y[NROWS * DMODEL];
static __device__ float g_S[(size_t)NBATCH * NHEADS * LSEQ * LSEQ];

// ---------------------------------------------------------------------------
__device__ __forceinline__ void bf16_split2(float x0, float x1,
                                            unsigned& hi_w, unsigned& lo_w) {
    asm("cvt.rn.bf16x2.f32 %0, %1, %2;" : "=r"(hi_w) : "f"(x1), "f"(x0));
    __nv_bfloat162 hv = *reinterpret_cast<__nv_bfloat162*>(&hi_w);
    float r0 = x0 - __bfloat162float(hv.x);
    float r1 = x1 - __bfloat162float(hv.y);
    asm("cvt.rn.bf16x2.f32 %0, %1, %2;" : "=r"(lo_w) : "f"(r1), "f"(r0));
}

__device__ __forceinline__ void mma16(float* c, const unsigned* a, const unsigned* b) {
    asm volatile(
        "mma.sync.aligned.m16n8k16.row.col.f32.bf16.bf16.f32 "
        "{%0,%1,%2,%3}, {%4,%5,%6,%7}, {%8,%9}, {%0,%1,%2,%3};"
        : "+f"(c[0]), "+f"(c[1]), "+f"(c[2]), "+f"(c[3])
        : "r"(a[0]), "r"(a[1]), "r"(a[2]), "r"(a[3]), "r"(b[0]), "r"(b[1]));
}

#define PAD_A 136
#define PAD_B 72

__device__ __forceinline__ void frag_a(const unsigned (*T)[PAD_A], int tig, int m,
                                       unsigned* a) {
    a[0] = T[tig    ][m    ];
    a[1] = T[tig    ][m + 8];
    a[2] = T[tig + 4][m    ];
    a[3] = T[tig + 4][m + 8];
}

// ---------------------------------------------------------------------------
// Dense NN GEMM with register-prefetch pipeline. bf16-3x, k16 MMA.
// BM=BN=128, BK=16, 8 warps. grid=(8, M/128).
// ---------------------------------------------------------------------------
__global__ __launch_bounds__(256, 2) void mma_nn_kernel(
    const float* __restrict__ A, const float* __restrict__ B,
    float* __restrict__ C, const float* __restrict__ R, int K)
{
    const int N = DMODEL;
    __shared__ unsigned AsH[8][PAD_A], AsL[8][PAD_A];
    __shared__ unsigned BsH[8][PAD_A], BsL[8][PAD_A];

    const int tid = threadIdx.x;
    const int wid = tid >> 5, lane = tid & 31;
    const int gid = lane >> 2, tig = lane & 3;
    const int wm = (wid & 1) * 64, wn = (wid >> 1) * 32;
    const int bm = blockIdx.y * 128, bn = blockIdx.x * 128;

    // load indices (fixed per thread)
    const int ar0 = tid >> 2,          ac0 = (tid & 3) << 2;          // A t=0
    const int ar1 = (tid + 256) >> 2,  ac1 = ((tid + 256) & 3) << 2;  // A t=1
    const int bk2 = tid >> 5,          bn4 = (tid & 31) << 2;         // B

    float acc[4][4][4] = {};
    float4 a0, a1, b0, b1;

    // prologue: load k0 = 0
    a0 = *(const float4*)(A + (size_t)(bm + ar0) * K + ac0);
    a1 = *(const float4*)(A + (size_t)(bm + ar1) * K + ac1);
    {
        const float* p = B + (size_t)(2 * bk2) * N + bn + bn4;
        b0 = *(const float4*)p;
        b1 = *(const float4*)(p + N);
    }

    for (int k0 = 0; k0 < K; k0 += 16) {
        __syncthreads();   // prev MMAs done before overwriting smem
        // split + store current regs
        {
            unsigned h0, l0, h1, l1;
            int k2 = ac0 >> 1;
            bf16_split2(a0.x, a0.y, h0, l0);
            bf16_split2(a0.z, a0.w, h1, l1);
            AsH[k2][ar0] = h0; AsL[k2][ar0] = l0;
            AsH[k2 + 1][ar0] = h1; AsL[k2 + 1][ar0] = l1;
            k2 = ac1 >> 1;
            bf16_split2(a1.x, a1.y, h0, l0);
            bf16_split2(a1.z, a1.w, h1, l1);
            AsH[k2][ar1] = h0; AsL[k2][ar1] = l0;
            AsH[k2 + 1][ar1] = h1; AsL[k2 + 1][ar1] = l1;
            unsigned h, l;
            bf16_split2(b0.x, b1.x, h, l); BsH[bk2][bn4]     = h; BsL[bk2][bn4]     = l;
            bf16_split2(b0.y, b1.y, h, l); BsH[bk2][bn4 + 1] = h; BsL[bk2][bn4 + 1] = l;
            bf16_split2(b0.z, b1.z, h, l); BsH[bk2][bn4 + 2] = h; BsL[bk2][bn4 + 2] = l;
            bf16_split2(b0.w, b1.w, h, l); BsH[bk2][bn4 + 3] = h; BsL[bk2][bn4 + 3] = l;
        }
        __syncthreads();
        // prefetch next tile (LDG latency overlaps MMAs below)
        if (k0 + 16 < K) {
            int kn = k0 + 16;
            a0 = *(const float4*)(A + (size_t)(bm + ar0) * K + kn + ac0);
            a1 = *(const float4*)(A + (size_t)(bm + ar1) * K + kn + ac1);
            const float* p = B + (size_t)(kn + 2 * bk2) * N + bn + bn4;
            b0 = *(const float4*)p;
            b1 = *(const float4*)(p + N);
        }
        // compute
        unsigned aH[4][4], aL[4][4];
        #pragma unroll
        for (int mf = 0; mf < 4; mf++) {
            frag_a(AsH, tig, wm + mf * 16 + gid, aH[mf]);
            frag_a(AsL, tig, wm + mf * 16 + gid, aL[mf]);
        }
        #pragma unroll
        for (int nf = 0; nf < 4; nf++) {
            int n = wn + nf * 8 + gid;
            unsigned bH[2] = { BsH[tig][n], BsH[tig + 4][n] };
            unsigned bL[2] = { BsL[tig][n], BsL[tig + 4][n] };
            #pragma unroll
            for (int mf = 0; mf < 4; mf++) {
                mma16(acc[mf][nf], aH[mf], bH);
                mma16(acc[mf][nf], aH[mf], bL);
                mma16(acc[mf][nf], aL[mf], bH);
            }
        }
    }

    #pragma unroll
    for (int mf = 0; mf < 4; mf++) {
        #pragma unroll
        for (int nf = 0; nf < 4; nf++) {
            int m = bm + wm + mf * 16 + gid;
            int n = bn + wn + nf * 8 + 2 * tig;
            float2 v0 = make_float2(acc[mf][nf][0], acc[mf][nf][1]);
            float2 v1 = make_float2(acc[mf][nf][2], acc[mf][nf][3]);
            if (R) {
                float2 r0 = *(const float2*)(R + (size_t)m * N + n);
                float2 r1 = *(const float2*)(R + (size_t)(m + 8) * N + n);
                v0.x += r0.x; v0.y += r0.y; v1.x += r1.x; v1.y += r1.y;
            }
            *(float2*)(C + (size_t)m * N + n) = v0;
            *(float2*)(C + (size_t)(m + 8) * N + n) = v1;
        }
    }
}

// ---------------------------------------------------------------------------
// Scores: per (b,h): S = 0.125 * Q @ K^T raw (masked), to scratch. Unchanged.
// ---------------------------------------------------------------------------
__global__ __launch_bounds__(256, 2) void mma_scores_kernel(
    const float* __restrict__ Qg, const float* __restrict__ Kg,
    float* __restrict__ S, const unsigned int* __restrict__ mask)
{
    const int z = blockIdx.z, b = z >> 4, h = z & 15;
    const float* Aq = Qg + (size_t)b * LSEQ * DMODEL + h * DHEAD;
    const float* Bk = Kg + (size_t)b * LSEQ * DMODEL + h * DHEAD;
    float* C = S + (size_t)z * LSEQ * LSEQ;
    const unsigned int* mb = mask + (size_t)b * LSEQ * LSEQ;

    __shared__ unsigned AsH[8][PAD_A], AsL[8][PAD_A];
    __shared__ unsigned BsH[8][PAD_A], BsL[8][PAD_A];

    const int tid = threadIdx.x;
    const int wid = tid >> 5, lane = tid & 31;
    const int gid = lane >> 2, tig = lane & 3;
    const int wm = (wid & 1) * 64, wn = (wid >> 1) * 32;
    const int bm = blockIdx.y * 128, bn = blockIdx.x * 128;

    float acc[4][4][4] = {};

    for (int k0 = 0; k0 < DHEAD; k0 += 16) {
        #pragma unroll
        for (int t = 0; t < 2; t++) {
            int id = tid + t * 256;
            int r = id >> 2, c = (id & 3) << 2, k2 = c >> 1;
            float4 v = *(const float4*)(Aq + (size_t)(bm + r) * DMODEL + k0 + c);
            unsigned h0, l0, h1, l1;
            bf16_split2(v.x, v.y, h0, l0);
            bf16_split2(v.z, v.w, h1, l1);
            AsH[k2][r] = h0; AsL[k2][r] = l0;
            AsH[k2 + 1][r] = h1; AsL[k2 + 1][r] = l1;
            float4 w = *(const float4*)(Bk + (size_t)(bn + r) * DMODEL + k0 + c);
            bf16_split2(w.x, w.y, h0, l0);
            bf16_split2(w.z, w.w, h1, l1);
            BsH[k2][r] = h0; BsL[k2][r] = l0;
            BsH[k2 + 1][r] = h1; BsL[k2 + 1][r] = l1;
        }
        __syncthreads();

        unsigned aH[4][4], aL[4][4];
        #pragma unroll
        for (int mf = 0; mf < 4; mf++) {
            frag_a(AsH, tig, wm + mf * 16 + gid, aH[mf]);
            frag_a(AsL, tig, wm + mf * 16 + gid, aL[mf]);
        }
        #pragma unroll
        for (int nf = 0; nf < 4; nf++) {
            int n = wn + nf * 8 + gid;
            unsigned bH[2] = { BsH[tig][n], BsH[tig + 4][n] };
            unsigned bL[2] = { BsL[tig][n], BsL[tig + 4][n] };
            #pragma unroll
            for (int mf = 0; mf < 4; mf++) {
                mma16(acc[mf][nf], aH[mf], bH);
                mma16(acc[mf][nf], aH[mf], bL);
                mma16(acc[mf][nf], aL[mf], bH);
            }
        }
        __syncthreads();
    }

    const float scale = 0.125f;
    #pragma unroll
    for (int mf = 0; mf < 4; mf++) {
        #pragma unroll
        for (int nf = 0; nf < 4; nf++) {
            int m = bm + wm + mf * 16 + gid;
            int n = bn + wn + nf * 8 + 2 * tig;
            #pragma unroll
            for (int half = 0; half < 2; half++) {
                int q = m + half * 8;
                float s0 = acc[mf][nf][half * 2]     * scale;
                float s1 = acc[mf][nf][half * 2 + 1] * scale;
                if (mb[(size_t)q * LSEQ + n]     != 0u) s0 = -1e9f;
                if (mb[(size_t)q * LSEQ + n + 1] != 0u) s1 = -1e9f;
                *(float2*)(C + (size_t)q * LSEQ + n) = make_float2(s0, s1);
            }
        }
    }
}

// ---------------------------------------------------------------------------
// Fused softmax + AV: per (b,h) block of 128 q-rows:
// phase 1: online max/sumexp over raw scores; phase 2: p = exp(s-m)*inv,
// write normalized attn to ATTN, bf16-split to smem, MMA with V.
// grid = (1, 8, 128).
// ---------------------------------------------------------------------------
__global__ __launch_bounds__(256, 2) void mma_av_fused_kernel(
    const float* __restrict__ S, const float* __restrict__ Vg,
    float* __restrict__ CTX, float* __restrict__ ATTN)
{
    const int z = blockIdx.z, b = z >> 4, h = z & 15;
    const float* A  = S + (size_t)z * LSEQ * LSEQ;
    const float* Bp = Vg + (size_t)b * LSEQ * DMODEL + h * DHEAD;
    float* C    = CTX  + (size_t)b * LSEQ * DMODEL + h * DHEAD;
    float* Aout = ATTN + (size_t)z * LSEQ * LSEQ;

    __shared__ unsigned AsH[8][PAD_A], AsL[8][PAD_A];
    __shared__ unsigned BsH[8][PAD_B], BsL[8][PAD_B];
    __shared__ float rowM[128], rowI[128];

    const int tid = threadIdx.x;
    const int wid = tid >> 5, lane = tid & 31;
    const int gid = lane >> 2, tig = lane & 3;
    const int wm = (wid & 1) * 64, wn = (wid >> 1) * 16;
    const int bm = blockIdx.y * 128;

    // ---- phase 1: online softmax stats, 2 threads per row ----
    {
        const int row = tid >> 1, half = tid & 1;
        const float* p = A + (size_t)(bm + row) * LSEQ + half * 512;
        float m = -1e30f, s = 0.0f;
        for (int i = 0; i < 512; i += 4) {
            float4 v = *(const float4*)(p + i);
            float mx = fmaxf(fmaxf(v.x, v.y), fmaxf(v.z, v.w));
            if (mx > m) { s *= __expf(m - mx); m = mx; }
            s += __expf(v.x - m) + __expf(v.y - m) + __expf(v.z - m) + __expf(v.w - m);
        }
        float m2 = __shfl_xor_sync(0xffffffffu, m, 1);
        float s2 = __shfl_xor_sync(0xffffffffu, s, 1);
        float mm = fmaxf(m, m2);
        float ss = s * __expf(m - mm) + s2 * __expf(m2 - mm);
        if (half == 0) { rowM[row] = mm; rowI[row] = 1.0f / ss; }
    }
    __syncthreads();

    // ---- phase 2: tile loop ----
    float acc[4][2][4] = {};

    for (int k0 = 0; k0 < LSEQ; k0 += 16) {
        #pragma unroll
        for (int t = 0; t < 2; t++) {
            int id = tid + t * 256;
            int r = id >> 2, c = (id & 3) << 2, k2 = c >> 1;
            float4 v = *(const float4*)(A + (size_t)(bm + r) * LSEQ + k0 + c);
            const float m = rowM[r], inv = rowI[r];
            v.x = __expf(v.x - m) * inv;
            v.y = __expf(v.y - m) * inv;
            v.z = __expf(v.z - m) * inv;
            v.w = __expf(v.w - m) * inv;
            *(float4*)(Aout + (size_t)(bm + r) * LSEQ + k0 + c) = v;
            unsigned h0, l0, h1, l1;
            bf16_split2(v.x, v.y, h0, l0);
            bf16_split2(v.z, v.w, h1, l1);
            AsH[k2][r] = h0; AsL[k2][r] = l0;
            AsH[k2 + 1][r] = h1; AsL[k2 + 1][r] = l1;
        }
        if (tid < 128) {
            int k2 = tid >> 4, n = (tid & 15) << 2;
            const float* p = Bp + (size_t)(k0 + 2 * k2) * DMODEL + n;
            float4 r0 = *(const float4*)p;
            float4 r1 = *(const float4*)(p + DMODEL);
            unsigned h, l;
            bf16_split2(r0.x, r1.x, h, l); BsH[k2][n]     = h; BsL[k2][n]     = l;
            bf16_split2(r0.y, r1.y, h, l); BsH[k2][n + 1] = h; BsL[k2][n + 1] = l;
            bf16_split2(r0.z, r1.z, h, l); BsH[k2][n + 2] = h; BsL[k2][n + 2] = l;
            bf16_split2(r0.w, r1.w, h, l); BsH[k2][n + 3] = h; BsL[k2][n + 3] = l;
        }
        __syncthreads();

        unsigned aH[4][4], aL[4][4];
        #pragma unroll
        for (int mf = 0; mf < 4; mf++) {
            frag_a(AsH, tig, wm + mf * 16 + gid, aH[mf]);
            frag_a(AsL, tig, wm + mf * 16 + gid, aL[mf]);
        }
        #pragma unroll
        for (int nf = 0; nf < 2; nf++) {
            int n = wn + nf * 8 + gid;
            unsigned bH[2] = { BsH[tig][n], BsH[tig + 4][n] };
            unsigned bL[2] = { BsL[tig][n], BsL[tig + 4][n] };
            #pragma unroll
            for (int mf = 0; mf < 4; mf++) {
                mma16(acc[mf][nf], aH[mf], bH);
                mma16(acc[mf][nf], aH[mf], bL);
                mma16(acc[mf][nf], aL[mf], bH);
            }
        }
        __syncthreads();
    }

    #pragma unroll
    for (int mf = 0; mf < 4; mf++) {
        #pragma unroll
        for (int nf = 0; nf < 2; nf++) {
            int m = bm + wm + mf * 16 + gid;
            int n = wn + nf * 8 + 2 * tig;
            *(float2*)(C + (size_t)m * DMODEL + n) =
                make_float2(acc[mf][nf][0], acc[mf][nf][1]);
            *(float2*)(C + (size_t)(m + 8) * DMODEL + n) =
                make_float2(acc[mf][nf][2], acc[mf][nf][3]);
        }
    }
}

// ---------------------------------------------------------------------------
__global__ __launch_bounds__(256) void ln_kernel(
    const float* __restrict__ Y, float* __restrict__ O,
    const float* __restrict__ gamma, const float* __restrict__ beta)
{
    __shared__ float red[256];
    const float* p = Y + (size_t)blockIdx.x * DMODEL;
    const int tid = threadIdx.x;
    float4 v = *(const float4*)(p + tid * 4);
    red[tid] = v.x + v.y + v.z + v.w;
    __syncthreads();
    for (int s = 128; s > 0; s >>= 1) {
        if (tid < s) red[tid] += red[tid + s];
        __syncthreads();
    }
    const float mu = red[0] * (1.0f / DMODEL);
    __syncthreads();
    const float dx = v.x - mu, dy = v.y - mu, dz = v.z - mu, dw = v.w - mu;
    red[tid] = dx * dx + dy * dy + dz * dz + dw * dw;
    __syncthreads();
    for (int s = 128; s > 0; s >>= 1) {
        if (tid < s) red[tid] += red[tid + s];
        __syncthreads();
    }
    const float rstd = rsqrtf(red[0] * (1.0f / DMODEL) + 1e-6f);
    const float4 g  = *(const float4*)(gamma + tid * 4);
    const float4 be = *(const float4*)(beta + tid * 4);
    float4 o;
    o.x = dx * rstd * g.x + be.x;
    o.y = dy * rstd * g.y + be.y;
    o.z = dz * rstd * g.z + be.z;
    o.w = dw * rstd * g.w + be.w;
    *(float4*)(O + (size_t)blockIdx.x * DMODEL + tid * 4) = o;
}

// ---------------------------------------------------------------------------
extern "C" void kernel_launch(void* const* d_in, const int* in_sizes, int n_in,
                              void* d_out, int out_size)
{
    const float* X    = (const float*)d_in[0];
    const unsigned int* mask = (const unsigned int*)d_in[1];
    const float* W_Q  = (const float*)d_in[2];
    const float* W_K  = (const float*)d_in[3];
    const float* W_V  = (const float*)d_in[4];
    const float* W_O  = (const float*)d_in[5];
    const float* gamma = (const float*)d_in[6];
    const float* beta  = (const float*)d_in[7];

    float *Qp, *Kp, *Vp, *Cp, *Yp, *Sp;
    cudaGetSymbolAddress((void**)&Qp, g_Q);
    cudaGetSymbolAddress((void**)&Kp, g_K);
    cudaGetSymbolAddress((void**)&Vp, g_V);
    cudaGetSymbolAddress((void**)&Cp, g_CTX);
    cudaGetSymbolAddress((void**)&Yp, g_Y);
    cudaGetSymbolAddress((void**)&Sp, g_S);

    const size_t LN_ELEMS   = (size_t)NROWS * DMODEL;
    const size_t ATTN_ELEMS = (size_t)NBATCH * NHEADS * LSEQ * LSEQ;

    float* out_ln;
    float* attn_out;
    if ((size_t)out_size >= LN_ELEMS + ATTN_ELEMS) {
        out_ln = (float*)d_out;
        attn_out = (float*)d_out + LN_ELEMS;
    } else if ((size_t)out_size == ATTN_ELEMS) {
        attn_out = (float*)d_out;
        out_ln = Yp;
    } else {
        out_ln = (float*)d_out;
        attn_out = Sp;   // attn not required; aliased scratch is safe (RMW same-thread)
    }

    dim3 thr(256);
    mma_nn_kernel<<<dim3(8, 64), thr>>>(X, W_Q, Qp, nullptr, DMODEL);
    mma_nn_kernel<<<dim3(8, 64), thr>>>(X, W_K, Kp, nullptr, DMODEL);
    mma_nn_kernel<<<dim3(8, 64), thr>>>(X, W_V, Vp, nullptr, DMODEL);
    mma_scores_kernel<<<dim3(8, 8, NBATCH * NHEADS), thr>>>(Qp, Kp, Sp, mask);
    mma_av_fused_kernel<<<dim3(1, 8, NBATCH * NHEADS), thr>>>(Sp, Vp, Cp, attn_out);
    mma_nn_kernel<<<dim3(8, 64), thr>>>(Cp, W_O, Yp, X, DMODEL);
    ln_kernel<<<dim3(NROWS), thr>>>(Yp, out_ln, gamma, beta);
}

// round 12
// speedup vs baseline: 1.1493x; 1.1493x over previous
#include <cuda_runtime.h>
#include <cuda_bf16.h>
#include <math.h>

#define LSEQ   1024
#define DMODEL 1024
#define NHEADS 16
#define DHEAD  64
#define NBATCH 8
#define NROWS  (NBATCH * LSEQ)   // 8192

static __device__ float g_Q[NROWS * DMODEL];
static __device__ float g_K[NROWS * DMODEL];
static __device__ float g_V[NROWS * DMODEL];
static __device__ float g_CTX[NROWS * DMODEL];
static __device__ float g_Y[NROWS * DMODEL];
static __device__ float g_S[(size_t)NBATCH * NHEADS * LSEQ * LSEQ]; // only used if attn not an output

// ---------------------------------------------------------------------------
__device__ __forceinline__ void bf16_split2(float x0, float x1,
                                            unsigned& hi_w, unsigned& lo_w) {
    asm("cvt.rn.bf16x2.f32 %0, %1, %2;" : "=r"(hi_w) : "f"(x1), "f"(x0));
    __nv_bfloat162 hv = *reinterpret_cast<__nv_bfloat162*>(&hi_w);
    float r0 = x0 - __bfloat162float(hv.x);
    float r1 = x1 - __bfloat162float(hv.y);
    asm("cvt.rn.bf16x2.f32 %0, %1, %2;" : "=r"(lo_w) : "f"(r1), "f"(r0));
}

__device__ __forceinline__ void mma16(float* c, const unsigned* a, const unsigned* b) {
    asm volatile(
        "mma.sync.aligned.m16n8k16.row.col.f32.bf16.bf16.f32 "
        "{%0,%1,%2,%3}, {%4,%5,%6,%7}, {%8,%9}, {%0,%1,%2,%3};"
        : "+f"(c[0]), "+f"(c[1]), "+f"(c[2]), "+f"(c[3])
        : "r"(a[0]), "r"(a[1]), "r"(a[2]), "r"(a[3]), "r"(b[0]), "r"(b[1]));
}

#define PAD_A 136
#define PAD_B 72

__device__ __forceinline__ void frag_a(const unsigned (*T)[PAD_A], int tig, int m,
                                       unsigned* a) {
    a[0] = T[tig    ][m    ];
    a[1] = T[tig    ][m + 8];
    a[2] = T[tig + 4][m    ];
    a[3] = T[tig + 4][m + 8];
}

// ---------------------------------------------------------------------------
// Dense NN GEMM (R9 version). bf16-3x, k16 MMA. BM=BN=128, BK=16.
// ---------------------------------------------------------------------------
__global__ __launch_bounds__(256, 2) void mma_nn_kernel(
    const float* __restrict__ A, const float* __restrict__ B,
    float* __restrict__ C, const float* __restrict__ R, int K)
{
    const int N = DMODEL;
    __shared__ unsigned AsH[8][PAD_A], AsL[8][PAD_A];
    __shared__ unsigned BsH[8][PAD_A], BsL[8][PAD_A];

    const int tid = threadIdx.x;
    const int wid = tid >> 5, lane = tid & 31;
    const int gid = lane >> 2, tig = lane & 3;
    const int wm = (wid & 1) * 64, wn = (wid >> 1) * 32;
    const int bm = blockIdx.y * 128, bn = blockIdx.x * 128;

    float acc[4][4][4] = {};

    for (int k0 = 0; k0 < K; k0 += 16) {
        #pragma unroll
        for (int t = 0; t < 2; t++) {
            int id = tid + t * 256;
            int r = id >> 2, c = (id & 3) << 2, k2 = c >> 1;
            float4 v = *(const float4*)(A + (size_t)(bm + r) * K + k0 + c);
            unsigned h0, l0, h1, l1;
            bf16_split2(v.x, v.y, h0, l0);
            bf16_split2(v.z, v.w, h1, l1);
            AsH[k2][r] = h0; AsL[k2][r] = l0;
            AsH[k2 + 1][r] = h1; AsL[k2 + 1][r] = l1;
        }
        {
            int k2 = tid >> 5, n = (tid & 31) << 2;
            const float* p = B + (size_t)(k0 + 2 * k2) * N + bn + n;
            float4 r0 = *(const float4*)p;
            float4 r1 = *(const float4*)(p + N);
            unsigned h, l;
            bf16_split2(r0.x, r1.x, h, l); BsH[k2][n]     = h; BsL[k2][n]     = l;
            bf16_split2(r0.y, r1.y, h, l); BsH[k2][n + 1] = h; BsL[k2][n + 1] = l;
            bf16_split2(r0.z, r1.z, h, l); BsH[k2][n + 2] = h; BsL[k2][n + 2] = l;
            bf16_split2(r0.w, r1.w, h, l); BsH[k2][n + 3] = h; BsL[k2][n + 3] = l;
        }
        __syncthreads();

        unsigned aH[4][4], aL[4][4];
        #pragma unroll
        for (int mf = 0; mf < 4; mf++) {
            frag_a(AsH, tig, wm + mf * 16 + gid, aH[mf]);
            frag_a(AsL, tig, wm + mf * 16 + gid, aL[mf]);
        }
        #pragma unroll
        for (int nf = 0; nf < 4; nf++) {
            int n = wn + nf * 8 + gid;
            unsigned bH[2] = { BsH[tig][n], BsH[tig + 4][n] };
            unsigned bL[2] = { BsL[tig][n], BsL[tig + 4][n] };
            #pragma unroll
            for (int mf = 0; mf < 4; mf++) {
                mma16(acc[mf][nf], aH[mf], bH);
                mma16(acc[mf][nf], aH[mf], bL);
                mma16(acc[mf][nf], aL[mf], bH);
            }
        }
        __syncthreads();
    }

    #pragma unroll
    for (int mf = 0; mf < 4; mf++) {
        #pragma unroll
        for (int nf = 0; nf < 4; nf++) {
            int m = bm + wm + mf * 16 + gid;
            int n = bn + wn + nf * 8 + 2 * tig;
            float2 v0 = make_float2(acc[mf][nf][0], acc[mf][nf][1]);
            float2 v1 = make_float2(acc[mf][nf][2], acc[mf][nf][3]);
            if (R) {
                float2 r0 = *(const float2*)(R + (size_t)m * N + n);
                float2 r1 = *(const float2*)(R + (size_t)(m + 8) * N + n);
                v0.x += r0.x; v0.y += r0.y; v1.x += r1.x; v1.y += r1.y;
            }
            *(float2*)(C + (size_t)m * N + n) = v0;
            *(float2*)(C + (size_t)(m + 8) * N + n) = v1;
        }
    }
}

// ---------------------------------------------------------------------------
// Flash attention: per block = one (b,h) and 128 q rows.
// Pass 1: stream K tiles (64 kv), S=Q@K^T, rowSum += exp (no max shift).
// Pass 2: recompute S, p = exp*inv, write fp32 attn, AV-MMA into ctx.
// Q resident in smem; K and P share a buffer. grid = (8 qtiles, 128 z).
// ---------------------------------------------------------------------------
__global__ __launch_bounds__(256, 2) void flash_attn_kernel(
    const float* __restrict__ Qg, const float* __restrict__ Kg,
    const float* __restrict__ Vg, const unsigned int* __restrict__ mask,
    float* __restrict__ CTX, float* __restrict__ ATTN)
{
    extern __shared__ unsigned sh[];
    unsigned (*QsH)[PAD_A] = (unsigned (*)[PAD_A])(sh);            // 32 rows
    unsigned (*QsL)[PAD_A] = (unsigned (*)[PAD_A])(sh + 4352);
    unsigned (*KPH)[PAD_A] = (unsigned (*)[PAD_A])(sh + 8704);     // K, then P
    unsigned (*KPL)[PAD_A] = (unsigned (*)[PAD_A])(sh + 13056);
    unsigned (*VsH)[PAD_B] = (unsigned (*)[PAD_B])(sh + 17408);    // 32 rows
    unsigned (*VsL)[PAD_B] = (unsigned (*)[PAD_B])(sh + 19712);
    float* rowSum = (float*)(sh + 22016);   // 128
    float* rowInv = (float*)(sh + 22144);   // 128

    const int z = blockIdx.y, b = z >> 4, h = z & 15;
    const float* Qp = Qg + (size_t)b * LSEQ * DMODEL + h * DHEAD;
    const float* Kp = Kg + (size_t)b * LSEQ * DMODEL + h * DHEAD;
    const float* Vp = Vg + (size_t)b * LSEQ * DMODEL + h * DHEAD;
    float* Cp   = CTX  + (size_t)b * LSEQ * DMODEL + h * DHEAD;
    float* Aout = ATTN + (size_t)z * LSEQ * LSEQ;
    const unsigned int* mb = mask + (size_t)b * LSEQ * LSEQ;

    const int tid = threadIdx.x;
    const int wid = tid >> 5, lane = tid & 31;
    const int gid = lane >> 2, tig = lane & 3;
    const int wm = (wid & 1) * 64, wn = (wid >> 1) * 16;
    const int bm = blockIdx.x * 128;

    // ---- load Q tile (128 x 64) resident, split bf16 ----
    #pragma unroll
    for (int t = 0; t < 8; t++) {
        int id = tid + t * 256;               // 0..2047
        int r = id >> 4, c = (id & 15) << 2, k2 = c >> 1;
        float4 v = *(const float4*)(Qp + (size_t)(bm + r) * DMODEL + c);
        unsigned h0, l0, h1, l1;
        bf16_split2(v.x, v.y, h0, l0);
        bf16_split2(v.z, v.w, h1, l1);
        QsH[k2][r] = h0; QsL[k2][r] = l0;
        QsH[k2 + 1][r] = h1; QsL[k2 + 1][r] = l1;
    }
    if (tid < 128) rowSum[tid] = 0.0f;
    __syncthreads();

    // ================= pass 1: row sums =================
    for (int j = 0; j < LSEQ; j += 64) {
        // load K tile (64 kv rows x 64 dims) -> [k2][kv] layout
        #pragma unroll
        for (int t = 0; t < 4; t++) {
            int id = tid + t * 256;           // 0..1023
            int lr = id >> 4, c = (id & 15) << 2, k2 = c >> 1;
            float4 v = *(const float4*)(Kp + (size_t)(j + lr) * DMODEL + c);
            unsigned h0, l0, h1, l1;
            bf16_split2(v.x, v.y, h0, l0);
            bf16_split2(v.z, v.w, h1, l1);
            KPH[k2][lr] = h0; KPL[k2][lr] = l0;
            KPH[k2 + 1][lr] = h1; KPL[k2 + 1][lr] = l1;
        }
        __syncthreads();

        float acc[4][2][4] = {};
        #pragma unroll
        for (int s = 0; s < 4; s++) {
            unsigned aH[4], aL[4];
            #pragma unroll
            for (int nf = 0; nf < 2; nf++) {
                int n = wn + nf * 8 + gid;
                unsigned bH[2] = { KPH[8*s + tig][n], KPH[8*s + tig + 4][n] };
                unsigned bL[2] = { KPL[8*s + tig][n], KPL[8*s + tig + 4][n] };
                #pragma unroll
                for (int mf = 0; mf < 4; mf++) {
                    int m = wm + mf * 16 + gid;
                    aH[0] = QsH[8*s + tig][m];     aH[1] = QsH[8*s + tig][m + 8];
                    aH[2] = QsH[8*s + tig + 4][m]; aH[3] = QsH[8*s + tig + 4][m + 8];
                    aL[0] = QsL[8*s + tig][m];     aL[1] = QsL[8*s + tig][m + 8];
                    aL[2] = QsL[8*s + tig + 4][m]; aL[3] = QsL[8*s + tig + 4][m + 8];
                    mma16(acc[mf][nf], aH, bH);
                    mma16(acc[mf][nf], aH, bL);
                    mma16(acc[mf][nf], aL, bH);
                }
            }
        }
        // masked exp row-sum
        #pragma unroll
        for (int mf = 0; mf < 4; mf++) {
            float s0 = 0.0f, s1 = 0.0f;
            int r0 = wm + mf * 16 + gid;
            #pragma unroll
            for (int nf = 0; nf < 2; nf++) {
                int c0 = wn + nf * 8 + 2 * tig;
                uint2 m0 = *(const uint2*)(mb + (size_t)(bm + r0) * LSEQ + j + c0);
                uint2 m1 = *(const uint2*)(mb + (size_t)(bm + r0 + 8) * LSEQ + j + c0);
                s0 += (m0.x ? 0.0f : __expf(acc[mf][nf][0] * 0.125f))
                    + (m0.y ? 0.0f : __expf(acc[mf][nf][1] * 0.125f));
                s1 += (m1.x ? 0.0f : __expf(acc[mf][nf][2] * 0.125f))
                    + (m1.y ? 0.0f : __expf(acc[mf][nf][3] * 0.125f));
            }
            s0 += __shfl_xor_sync(0xffffffffu, s0, 1);
            s0 += __shfl_xor_sync(0xffffffffu, s0, 2);
            s1 += __shfl_xor_sync(0xffffffffu, s1, 1);
            s1 += __shfl_xor_sync(0xffffffffu, s1, 2);
            if (tig == 0) {
                atomicAdd(&rowSum[r0], s0);
                atomicAdd(&rowSum[r0 + 8], s1);
            }
        }
        __syncthreads();
    }
    if (tid < 128) rowInv[tid] = 1.0f / rowSum[tid];
    __syncthreads();

    // ================= pass 2: attn write + AV =================
    float ctx[4][2][4] = {};

    for (int j = 0; j < LSEQ; j += 64) {
        // load K tile
        #pragma unroll
        for (int t = 0; t < 4; t++) {
            int id = tid + t * 256;
            int lr = id >> 4, c = (id & 15) << 2, k2 = c >> 1;
            float4 v = *(const float4*)(Kp + (size_t)(j + lr) * DMODEL + c);
            unsigned h0, l0, h1, l1;
            bf16_split2(v.x, v.y, h0, l0);
            bf16_split2(v.z, v.w, h1, l1);
            KPH[k2][lr] = h0; KPL[k2][lr] = l0;
            KPH[k2 + 1][lr] = h1; KPL[k2 + 1][lr] = l1;
        }
        // load V tile (64 kv x 64 d) -> [kv2][d] (pair kv rows)
        #pragma unroll
        for (int t = 0; t < 2; t++) {
            int id = tid + t * 256;           // 0..511
            int kv2 = id >> 4, d = (id & 15) << 2;
            const float* p = Vp + (size_t)(j + 2 * kv2) * DMODEL + d;
            float4 r0 = *(const float4*)p;
            float4 r1 = *(const float4*)(p + DMODEL);
            unsigned hh, ll;
            bf16_split2(r0.x, r1.x, hh, ll); VsH[kv2][d]     = hh; VsL[kv2][d]     = ll;
            bf16_split2(r0.y, r1.y, hh, ll); VsH[kv2][d + 1] = hh; VsL[kv2][d + 1] = ll;
            bf16_split2(r0.z, r1.z, hh, ll); VsH[kv2][d + 2] = hh; VsL[kv2][d + 2] = ll;
            bf16_split2(r0.w, r1.w, hh, ll); VsH[kv2][d + 3] = hh; VsL[kv2][d + 3] = ll;
        }
        __syncthreads();

        // S = Q @ K^T for this tile
        float acc[4][2][4] = {};
        #pragma unroll
        for (int s = 0; s < 4; s++) {
            unsigned aH[4], aL[4];
            #pragma unroll
            for (int nf = 0; nf < 2; nf++) {
                int n = wn + nf * 8 + gid;
                unsigned bH[2] = { KPH[8*s + tig][n], KPH[8*s + tig + 4][n] };
                unsigned bL[2] = { KPL[8*s + tig][n], KPL[8*s + tig + 4][n] };
                #pragma unroll
                for (int mf = 0; mf < 4; mf++) {
                    int m = wm + mf * 16 + gid;
                    aH[0] = QsH[8*s + tig][m];     aH[1] = QsH[8*s + tig][m + 8];
                    aH[2] = QsH[8*s + tig + 4][m]; aH[3] = QsH[8*s + tig + 4][m + 8];
                    aL[0] = QsL[8*s + tig][m];     aL[1] = QsL[8*s + tig][m + 8];
                    aL[2] = QsL[8*s + tig + 4][m]; aL[3] = QsL[8*s + tig + 4][m + 8];
                    mma16(acc[mf][nf], aH, bH);
                    mma16(acc[mf][nf], aH, bL);
                    mma16(acc[mf][nf], aL, bH);
                }
            }
        }
        __syncthreads();   // all S-mma done before P overwrites K buffer

        // p = exp * inv, write attn, store P (bf16 hi/lo) into KP buffer
        #pragma unroll
        for (int mf = 0; mf < 4; mf++) {
            int r0 = wm + mf * 16 + gid;
            float i0 = rowInv[r0], i1 = rowInv[r0 + 8];
            #pragma unroll
            for (int nf = 0; nf < 2; nf++) {
                int c0 = wn + nf * 8 + 2 * tig;
                uint2 m0 = *(const uint2*)(mb + (size_t)(bm + r0) * LSEQ + j + c0);
                uint2 m1 = *(const uint2*)(mb + (size_t)(bm + r0 + 8) * LSEQ + j + c0);
                float p0 = m0.x ? 0.0f : __expf(acc[mf][nf][0] * 0.125f) * i0;
                float p1 = m0.y ? 0.0f : __expf(acc[mf][nf][1] * 0.125f) * i0;
                float p2 = m1.x ? 0.0f : __expf(acc[mf][nf][2] * 0.125f) * i1;
                float p3 = m1.y ? 0.0f : __expf(acc[mf][nf][3] * 0.125f) * i1;
                *(float2*)(Aout + (size_t)(bm + r0) * LSEQ + j + c0) = make_float2(p0, p1);
                *(float2*)(Aout + (size_t)(bm + r0 + 8) * LSEQ + j + c0) = make_float2(p2, p3);
                int k2 = c0 >> 1;
                unsigned hh, ll;
                bf16_split2(p0, p1, hh, ll);
                KPH[k2][r0] = hh; KPL[k2][r0] = ll;
                bf16_split2(p2, p3, hh, ll);
                KPH[k2][r0 + 8] = hh; KPL[k2][r0 + 8] = ll;
            }
        }
        __syncthreads();

        // ctx += P @ V
        #pragma unroll
        for (int s = 0; s < 4; s++) {
            unsigned aH[4], aL[4];
            #pragma unroll
            for (int nf = 0; nf < 2; nf++) {
                int n = wn + nf * 8 + gid;
                unsigned bH[2] = { VsH[8*s + tig][n], VsH[8*s + tig + 4][n] };
                unsigned bL[2] = { VsL[8*s + tig][n], VsL[8*s + tig + 4][n] };
                #pragma unroll
                for (int mf = 0; mf < 4; mf++) {
                    int m = wm + mf * 16 + gid;
                    aH[0] = KPH[8*s + tig][m];     aH[1] = KPH[8*s + tig][m + 8];
                    aH[2] = KPH[8*s + tig + 4][m]; aH[3] = KPH[8*s + tig + 4][m + 8];
                    aL[0] = KPL[8*s + tig][m];     aL[1] = KPL[8*s + tig][m + 8];
                    aL[2] = KPL[8*s + tig + 4][m]; aL[3] = KPL[8*s + tig + 4][m + 8];
                    mma16(ctx[mf][nf], aH, bH);
                    mma16(ctx[mf][nf], aH, bL);
                    mma16(ctx[mf][nf], aL, bH);
                }
            }
        }
        __syncthreads();
    }

    #pragma unroll
    for (int mf = 0; mf < 4; mf++) {
        #pragma unroll
        for (int nf = 0; nf < 2; nf++) {
            int m = bm + wm + mf * 16 + gid;
            int n = wn + nf * 8 + 2 * tig;
            *(float2*)(Cp + (size_t)m * DMODEL + n) =
                make_float2(ctx[mf][nf][0], ctx[mf][nf][1]);
            *(float2*)(Cp + (size_t)(m + 8) * DMODEL + n) =
                make_float2(ctx[mf][nf][2], ctx[mf][nf][3]);
        }
    }
}

// ---------------------------------------------------------------------------
__global__ __launch_bounds__(256) void ln_kernel(
    const float* __restrict__ Y, float* __restrict__ O,
    const float* __restrict__ gamma, const float* __restrict__ beta)
{
    __shared__ float red[256];
    const float* p = Y + (size_t)blockIdx.x * DMODEL;
    const int tid = threadIdx.x;
    float4 v = *(const float4*)(p + tid * 4);
    red[tid] = v.x + v.y + v.z + v.w;
    __syncthreads();
    for (int s = 128; s > 0; s >>= 1) {
        if (tid < s) red[tid] += red[tid + s];
        __syncthreads();
    }
    const float mu = red[0] * (1.0f / DMODEL);
    __syncthreads();
    const float dx = v.x - mu, dy = v.y - mu, dz = v.z - mu, dw = v.w - mu;
    red[tid] = dx * dx + dy * dy + dz * dz + dw * dw;
    __syncthreads();
    for (int s = 128; s > 0; s >>= 1) {
        if (tid < s) red[tid] += red[tid + s];
        __syncthreads();
    }
    const float rstd = rsqrtf(red[0] * (1.0f / DMODEL) + 1e-6f);
    const float4 g  = *(const float4*)(gamma + tid * 4);
    const float4 be = *(const float4*)(beta + tid * 4);
    float4 o;
    o.x = dx * rstd * g.x + be.x;
    o.y = dy * rstd * g.y + be.y;
    o.z = dz * rstd * g.z + be.z;
    o.w = dw * rstd * g.w + be.w;
    *(float4*)(O + (size_t)blockIdx.x * DMODEL + tid * 4) = o;
}

// ---------------------------------------------------------------------------
#define FLASH_SMEM (22272 * 4)

extern "C" void kernel_launch(void* const* d_in, const int* in_sizes, int n_in,
                              void* d_out, int out_size)
{
    const float* X    = (const float*)d_in[0];
    const unsigned int* mask = (const unsigned int*)d_in[1];
    const float* W_Q  = (const float*)d_in[2];
    const float* W_K  = (const float*)d_in[3];
    const float* W_V  = (const float*)d_in[4];
    const float* W_O  = (const float*)d_in[5];
    const float* gamma = (const float*)d_in[6];
    const float* beta  = (const float*)d_in[7];

    float *Qp, *Kp, *Vp, *Cp, *Yp, *Sp;
    cudaGetSymbolAddress((void**)&Qp, g_Q);
    cudaGetSymbolAddress((void**)&Kp, g_K);
    cudaGetSymbolAddress((void**)&Vp, g_V);
    cudaGetSymbolAddress((void**)&Cp, g_CTX);
    cudaGetSymbolAddress((void**)&Yp, g_Y);
    cudaGetSymbolAddress((void**)&Sp, g_S);

    static int smem_set = 0;
    if (!smem_set) {
        cudaFuncSetAttribute(flash_attn_kernel,
                             cudaFuncAttributeMaxDynamicSharedMemorySize, FLASH_SMEM);
        smem_set = 1;
    }

    const size_t LN_ELEMS   = (size_t)NROWS * DMODEL;
    const size_t ATTN_ELEMS = (size_t)NBATCH * NHEADS * LSEQ * LSEQ;

    float* out_ln;
    float* attn_out;
    if ((size_t)out_size >= LN_ELEMS + ATTN_ELEMS) {
        out_ln = (float*)d_out;
        attn_out = (float*)d_out + LN_ELEMS;
    } else if ((size_t)out_size == ATTN_ELEMS) {
        attn_out = (float*)d_out;
        out_ln = Yp;
    } else {
        out_ln = (float*)d_out;
        attn_out = Sp;
    }

    dim3 thr(256);
    mma_nn_kernel<<<dim3(8, 64), thr>>>(X, W_Q, Qp, nullptr, DMODEL);
    mma_nn_kernel<<<dim3(8, 64), thr>>>(X, W_K, Kp, nullptr, DMODEL);
    mma_nn_kernel<<<dim3(8, 64), thr>>>(X, W_V, Vp, nullptr, DMODEL);
    flash_attn_kernel<<<dim3(8, NBATCH * NHEADS), thr, FLASH_SMEM>>>(
        Qp, Kp, Vp, mask, Cp, attn_out);
    mma_nn_kernel<<<dim3(8, 64), thr>>>(Cp, W_O, Yp, X, DMODEL);
    ln_kernel<<<dim3(NROWS), thr>>>(Yp, out_ln, gamma, beta);
}